// round 6
// baseline (speedup 1.0000x reference)
#include <cuda_runtime.h>

// ---------------------------------------------------------------------------
// Q_NetWork: time-LSTM (in=10, hid=32) over T=16384 steps, feeding three
// masked LSTMs (in=32, hid=40), fused MLP -> scalar.
//
// R6 changes vs R5 (3.44 ms):
//   * producer matvec on 4 accumulators (dep chain 8 -> 4) + packed f32x2 add
//     reduction.
//   * sigmoid's 0.5 prescale folded into gx (K1) and weight registers
//     (prologue) -> no per-step select/mul before MUFU tanh.
//   * warp 4 = dedicated publisher: producers release a CTA-scope smem step
//     counter (1 cheap STS.RELEASE by tid0 per step); warp 4 does the gpu
//     fence + g_progress store off the critical path.
//   * consumer: h_sh double-buffered, 4 -> 3 __syncthreads per consumed step.
// ---------------------------------------------------------------------------

#define TSTEPS 16384
#define NITEMS 1000

typedef unsigned long long ull;

// global scratch (device globals: allocation-free per harness rules)
__device__ float g_gx[TSTEPS * 128];   // 8 MB: [t][row(gate*32+elem)] preacts
__device__ float g_ys[TSTEPS * 32];    // 2 MB: time-LSTM hidden states
__device__ float g_H[3][40];           // final hidden per mask type
__device__ int   g_progress;           // producer progress (steps completed)

// ---- fast math helpers ----------------------------------------------------
__device__ __forceinline__ float ftanh_(float x) {
    float y; asm("tanh.approx.f32 %0, %1;" : "=f"(y) : "f"(x)); return y;
}

// ---- scoped sync primitives ----------------------------------------------
__device__ __forceinline__ void fence_gpu() {
    asm volatile("fence.acq_rel.gpu;" ::: "memory");
}
__device__ __forceinline__ void st_relaxed_gpu(int* p, int v) {
    asm volatile("st.relaxed.gpu.global.b32 [%0], %1;" :: "l"(p), "r"(v) : "memory");
}
__device__ __forceinline__ int ld_acquire_gpu(const int* p) {
    int v; asm volatile("ld.acquire.gpu.global.b32 %0, [%1];" : "=r"(v) : "l"(p) : "memory");
    return v;
}
__device__ __forceinline__ unsigned smem_u32(const void* p) {
    unsigned a;
    asm("{ .reg .u64 t; cvta.to.shared.u64 t, %1; cvt.u32.u64 %0, t; }"
        : "=r"(a) : "l"(p));
    return a;
}
__device__ __forceinline__ void st_release_cta_shared(unsigned addr, int v) {
    asm volatile("st.release.cta.shared.b32 [%0], %1;" :: "r"(addr), "r"(v) : "memory");
}
__device__ __forceinline__ int ld_acquire_cta_shared(unsigned addr) {
    int v; asm volatile("ld.acquire.cta.shared.b32 %0, [%1];" : "=r"(v) : "r"(addr) : "memory");
    return v;
}
#define BAR_SYNC(id)   asm volatile("bar.sync %0, 128;"   :: "n"(id) : "memory")

// ---- packed f32x2 ops (sm_103a) -------------------------------------------
__device__ __forceinline__ ull pack2(float lo, float hi) {
    ull r; asm("mov.b64 %0, {%1,%2};" : "=l"(r) : "f"(lo), "f"(hi)); return r;
}
__device__ __forceinline__ void unpack2(ull v, float& lo, float& hi) {
    asm("mov.b64 {%0,%1}, %2;" : "=f"(lo), "=f"(hi) : "l"(v));
}
__device__ __forceinline__ void ffma2(ull& acc, ull a, ull b) {
    asm("fma.rn.f32x2 %0, %1, %2, %0;" : "+l"(acc) : "l"(a), "l"(b));
}
__device__ __forceinline__ ull add2(ull a, ull b) {
    ull r; asm("add.rn.f32x2 %0, %1, %2;" : "=l"(r) : "l"(a), "l"(b)); return r;
}
__device__ __forceinline__ ull mul2(ull a, ull b) {
    ull r; asm("mul.rn.f32x2 %0, %1, %2;" : "=l"(r) : "l"(a), "l"(b)); return r;
}
__device__ __forceinline__ float red2(ull v) {
    float lo, hi; unpack2(v, lo, hi); return lo + hi;
}

// ---------------------------------------------------------------------------
// K1: per-t gate preactivations for the time LSTM (fully parallel).
// Row r = gate*32 + elem, stored at g_gx[t*128 + r].
// Sigmoid gates (gate != 2) are PRE-SCALED by 0.5 (sigmoid(z)=0.5*tanh(0.5z)+0.5).
// ---------------------------------------------------------------------------
__global__ void k_precompute_gx(const int* __restrict__ items,
                                const int* __restrict__ types,
                                const float* __restrict__ dwell,
                                const float* __restrict__ item_emb,
                                const float* __restrict__ click,
                                const float* __restrict__ purchase,
                                const float* __restrict__ skip,
                                const float* __restrict__ Wih,
                                const float* __restrict__ bih,
                                const float* __restrict__ bhh)
{
    int t = blockIdx.x;
    int tid = threadIdx.x;   // 128 threads

    if (t == 0 && tid == 0) g_progress = 0;  // reset before pipeline kernel

    __shared__ float ie[32];
    __shared__ float xs[10];

    if (tid < 32) ie[tid] = item_emb[tid * NITEMS + items[t]];
    __syncthreads();

    if (tid < 9) {
        int ty = types[t];
        const float* P = (ty == 0) ? click : (ty == 1) ? purchase : skip;
        P += tid * 32;
        float s = 0.0f;
#pragma unroll
        for (int j = 0; j < 32; j++) s += P[j] * ie[j];
        xs[1 + tid] = s;
    } else if (tid == 9) {
        xs[0] = dwell[t];
    }
    __syncthreads();

    float acc = bih[tid] + bhh[tid];
    const float* w = Wih + tid * 10;
#pragma unroll
    for (int i = 0; i < 10; i++) acc += w[i] * xs[i];
    if ((tid >> 5) != 2) acc *= 0.5f;    // fold sigmoid prescale
    g_gx[t * 128 + tid] = acc;
}

// ---------------------------------------------------------------------------
// K2: persistent pipeline. grid = 4 blocks x 160 threads.
//   block 0: warps 0-3 = producer (time LSTM; warp w lane l owns gate (l>>3)
//            of element 8w+(l&7)); warp 4 lane 0 = progress publisher.
//   blocks 1..3: consumers for mask types 1 (p), 0 (c), 2 (s)
// ---------------------------------------------------------------------------
__global__ void __launch_bounds__(160, 1)
k_pipeline(const int* __restrict__ types,
           const float* __restrict__ time_Whh,
           const float* __restrict__ p_Wih, const float* __restrict__ p_Whh,
           const float* __restrict__ p_bih, const float* __restrict__ p_bhh,
           const float* __restrict__ c_Wih, const float* __restrict__ c_Whh,
           const float* __restrict__ c_bih, const float* __restrict__ c_bhh,
           const float* __restrict__ s_Wih, const float* __restrict__ s_Whh,
           const float* __restrict__ s_bih, const float* __restrict__ s_bhh)
{
    int tid = threadIdx.x;

    if (blockIdx.x == 0) {
        __shared__ __align__(16) float h_buf[2][32];
        __shared__ int s_cnt;

        if (tid == 0) s_cnt = 0;
        __syncthreads();                  // all 160: s_cnt init visible
        unsigned cnt_a = smem_u32(&s_cnt);

        if (tid >= 128) {
            // ------------- publisher: warp 4 lane 0 -------------
            if (tid != 128) return;
            int last = 0;
            while (last < TSTEPS) {
                int c = ld_acquire_cta_shared(cnt_a);
                if (c > last && c <= TSTEPS) {
                    fence_gpu();                     // cumulative: makes the
                    st_relaxed_gpu(&g_progress, c);  // CTA-HB'd ys writes gpu-visible
                    last = c;
                } else {
                    __nanosleep(32);
                }
            }
            return;
        }

        // ---------------- producer: time LSTM, 4 warps, 1 bar/step --------
        int wid = tid >> 5, l = tid & 31;
        int gate = l >> 3, eloc = l & 7;
        int e = wid * 8 + eloc;           // element 0..31
        int row = gate * 32 + e;          // Whh / gx row
        bool isg = (gate == 2);

        ull w2[16];
        {
            const ull* wp = reinterpret_cast<const ull*>(time_Whh + row * 32);
            ull half2c = pack2(0.5f, 0.5f);
#pragma unroll
            for (int i = 0; i < 16; i++) {
                ull w = wp[i];
                w2[i] = isg ? w : mul2(w, half2c);   // fold sigmoid prescale
            }
        }
        float c = 0.0f;
        if (l < 8) h_buf[0][e] = 0.0f;    // lanes 0..7 of each warp init 8 elems
        float gx = g_gx[row];             // t = 0
        BAR_SYNC(1);

        for (int t = 0; t < TSTEPS; t++) {
            if (tid == 0) st_release_cta_shared(cnt_a, t);   // steps 0..t-1 done
            // prefetch next step's preact (LDG hidden behind the step)
            float gxn = (t + 1 < TSTEPS) ? g_gx[(t + 1) * 128 + row] : 0.0f;

            ull a0 = pack2(gx, 0.0f);
            ull a1 = pack2(0.0f, 0.0f);
            ull a2 = pack2(0.0f, 0.0f);
            ull a3 = pack2(0.0f, 0.0f);
            const ulonglong2* hp = reinterpret_cast<const ulonglong2*>(h_buf[t & 1]);
#pragma unroll
            for (int q = 0; q < 4; q++) {
                ulonglong2 hv0 = hp[2 * q];
                ulonglong2 hv1 = hp[2 * q + 1];
                ffma2(a0, w2[4 * q],     hv0.x);
                ffma2(a1, w2[4 * q + 1], hv0.y);
                ffma2(a2, w2[4 * q + 2], hv1.x);
                ffma2(a3, w2[4 * q + 3], hv1.y);
            }
            float gsum = red2(add2(add2(a0, a1), add2(a2, a3)));
            float tv = ftanh_(gsum);                    // arg already prescaled
            float v = isg ? tv : fmaf(0.5f, tv, 0.5f);

            // intra-warp gate exchange (all gates of elem e live in this warp)
            float iv = __shfl_sync(0xffffffffu, v, eloc);
            float fv = __shfl_sync(0xffffffffu, v, 8 + eloc);
            float gg = __shfl_sync(0xffffffffu, v, 16 + eloc);
            float ov = __shfl_sync(0xffffffffu, v, 24 + eloc);

            c = fmaf(fv, c, iv * gg);          // replicated across gate-lanes
            float h = ov * ftanh_(c);

            if (l < 8) {
                h_buf[(t + 1) & 1][e] = h;
                g_ys[t * 32 + e] = h;
            }
            BAR_SYNC(1);                       // single barrier per step
            gx = gxn;
        }
        if (tid == 0) st_release_cta_shared(cnt_a, TSTEPS);
    } else {
        // ---------------- consumer: masked LSTM ----------------
        __shared__ unsigned char tysh[TSTEPS];   // 16 KB
        __shared__ __align__(16) float h_sh[2][40];
        __shared__ __align__(16) float x_sh[32];
        __shared__ float gsh[160];

        int b = blockIdx.x;
        int myType = (b == 1) ? 1 : (b == 2) ? 0 : 2;
        const float* Wih = (b == 1) ? p_Wih : (b == 2) ? c_Wih : s_Wih;
        const float* Whh = (b == 1) ? p_Whh : (b == 2) ? c_Whh : s_Whh;
        const float* bih = (b == 1) ? p_bih : (b == 2) ? c_bih : s_bih;
        const float* bhh = (b == 1) ? p_bhh : (b == 2) ? c_bhh : s_bhh;

        for (int i = tid; i < TSTEPS; i += 160)
            tysh[i] = (unsigned char)types[i];

        bool isg = (tid / 40 == 2);              // rows 80..119 = g-gate
        ull wih2[16], whh2[20];
        {
            ull half2c = pack2(0.5f, 0.5f);
            const ull* p = reinterpret_cast<const ull*>(Wih) + tid * 16;
#pragma unroll
            for (int i = 0; i < 16; i++) { ull w = p[i]; wih2[i] = isg ? w : mul2(w, half2c); }
            const ull* q = reinterpret_cast<const ull*>(Whh) + tid * 20;
#pragma unroll
            for (int i = 0; i < 20; i++) { ull w = q[i]; whh2[i] = isg ? w : mul2(w, half2c); }
        }
        float bsum = bih[tid] + bhh[tid];
        if (!isg) bsum *= 0.5f;
        float c = 0.0f;
        if (tid < 40) { h_sh[0][tid] = 0.0f; }
        __syncthreads();

        int seen = 0;
        int par = 0;
        for (int t = 0; t < TSTEPS; t++) {
            if (tysh[t] != (unsigned char)myType) continue;   // uniform across block

            if (tid == 0 && seen <= t) {
                while ((seen = ld_acquire_gpu(&g_progress)) <= t) { }
            }
            __syncthreads();                                   // (1) spin done

            if (tid < 32) x_sh[tid] = __ldcg(&g_ys[t * 32 + tid]);
            __syncthreads();                                   // (2) x & prev h ready

            ull a0 = pack2(bsum, 0.0f);
            ull a1 = pack2(0.0f, 0.0f);
            ull a2 = pack2(0.0f, 0.0f);
            ull a3 = pack2(0.0f, 0.0f);
            const ulonglong2* xp = reinterpret_cast<const ulonglong2*>(x_sh);
#pragma unroll
            for (int q = 0; q < 8; q++) {
                ffma2(a0, wih2[2 * q], xp[q].x);
                ffma2(a1, wih2[2 * q + 1], xp[q].y);
            }
            const ulonglong2* hp = reinterpret_cast<const ulonglong2*>(h_sh[par]);
#pragma unroll
            for (int q = 0; q < 10; q++) {
                ffma2(a2, whh2[2 * q], hp[q].x);
                ffma2(a3, whh2[2 * q + 1], hp[q].y);
            }
            float g = red2(add2(add2(a0, a1), add2(a2, a3)));
            float tv = ftanh_(g);
            float v = isg ? tv : fmaf(0.5f, tv, 0.5f);
            gsh[tid] = v;
            __syncthreads();                                   // (3) gates ready

            if (tid < 40) {
                float ig = gsh[tid], fg = gsh[40 + tid];
                float gg = gsh[80 + tid], og = gsh[120 + tid];
                c = fg * c + ig * gg;
                h_sh[par ^ 1][tid] = og * ftanh_(c);
            }
            par ^= 1;
            // no 4th barrier: next step's (1)/(2) order h_sh/gsh reuse
        }

        if (tid < 40) g_H[myType][tid] = h_sh[par][tid];
    }
}

// ---------------------------------------------------------------------------
// K3: fusion + MLP -> scalar
// fusion = [next_e(32), user_e(32), H_r(32), H_s(40), H_c(40), H_p(40)]
// ---------------------------------------------------------------------------
__global__ void k_mlp(const int* __restrict__ user,
                      const int* __restrict__ nextitem,
                      const float* __restrict__ item_emb,
                      const float* __restrict__ user_emb,
                      const float* __restrict__ out1_W,
                      const float* __restrict__ out1_b,
                      const float* __restrict__ out2_W,
                      const float* __restrict__ out2_b,
                      float* __restrict__ out)
{
    __shared__ float f[216];
    __shared__ float r16[16];
    int tid = threadIdx.x;   // 64 threads
    int u = user[0], ni = nextitem[0];

    if (tid < 32) {
        f[tid]      = item_emb[tid * NITEMS + ni];
        f[32 + tid] = user_emb[tid * NITEMS + u];
        f[64 + tid] = g_ys[(TSTEPS - 1) * 32 + tid];   // H_r
    }
    if (tid < 40) {
        f[96 + tid]  = g_H[2][tid];   // H_s (type 2)
        f[136 + tid] = g_H[0][tid];   // H_c (type 0)
        f[176 + tid] = g_H[1][tid];   // H_p (type 1)
    }
    __syncthreads();

    if (tid < 16) {
        float acc = out1_b[tid];
        const float* w = out1_W + tid * 216;
        for (int k = 0; k < 216; k++) acc += w[k] * f[k];
        r16[tid] = fmaxf(acc, 0.0f);
    }
    __syncthreads();

    if (tid == 0) {
        float acc = out2_b[0];
        for (int k = 0; k < 16; k++) acc += out2_W[k] * r16[k];
        out[0] = acc;
    }
}

// ---------------------------------------------------------------------------
extern "C" void kernel_launch(void* const* d_in, const int* in_sizes, int n_in,
                              void* d_out, int out_size)
{
    const int*   user      = (const int*)  d_in[0];
    const int*   nextitem  = (const int*)  d_in[1];
    const int*   seq_items = (const int*)  d_in[2];
    const int*   seq_types = (const int*)  d_in[3];
    const float* dwell     = (const float*)d_in[4];
    const float* item_emb  = (const float*)d_in[5];
    const float* user_emb  = (const float*)d_in[6];
    const float* click     = (const float*)d_in[7];
    const float* purchase  = (const float*)d_in[8];
    const float* skipp     = (const float*)d_in[9];
    const float* time_Wih  = (const float*)d_in[10];
    const float* time_Whh  = (const float*)d_in[11];
    const float* time_bih  = (const float*)d_in[12];
    const float* time_bhh  = (const float*)d_in[13];
    const float* p_Wih     = (const float*)d_in[14];
    const float* p_Whh     = (const float*)d_in[15];
    const float* p_bih     = (const float*)d_in[16];
    const float* p_bhh     = (const float*)d_in[17];
    const float* c_Wih     = (const float*)d_in[18];
    const float* c_Whh     = (const float*)d_in[19];
    const float* c_bih     = (const float*)d_in[20];
    const float* c_bhh     = (const float*)d_in[21];
    const float* s_Wih     = (const float*)d_in[22];
    const float* s_Whh     = (const float*)d_in[23];
    const float* s_bih     = (const float*)d_in[24];
    const float* s_bhh     = (const float*)d_in[25];
    const float* out1_W    = (const float*)d_in[26];
    const float* out1_b    = (const float*)d_in[27];
    const float* out2_W    = (const float*)d_in[28];
    const float* out2_b    = (const float*)d_in[29];

    k_precompute_gx<<<TSTEPS, 128>>>(seq_items, seq_types, dwell, item_emb,
                                     click, purchase, skipp,
                                     time_Wih, time_bih, time_bhh);

    k_pipeline<<<4, 160>>>(seq_types, time_Whh,
                           p_Wih, p_Whh, p_bih, p_bhh,
                           c_Wih, c_Whh, c_bih, c_bhh,
                           s_Wih, s_Whh, s_bih, s_bhh);

    k_mlp<<<1, 64>>>(user, nextitem, item_emb, user_emb,
                     out1_W, out1_b, out2_W, out2_b, (float*)d_out);
}

// round 7
// speedup vs baseline: 1.1575x; 1.1575x over previous
#include <cuda_runtime.h>

// ---------------------------------------------------------------------------
// Q_NetWork: time-LSTM (in=10, hid=32) over T=16384 steps, feeding three
// masked LSTMs (in=32, hid=40), fused MLP -> scalar.
//
// R7 = R5 skeleton (3.44 ms, best) + local-only wins from R6:
//   * producer matvec on 4 accumulators + packed add.f32x2 reduction
//   * sigmoid 0.5 prescale folded into gx (K1) and weight registers
//   * NO publisher warp (R6's regression: spin warp shared SMSP 0 with
//     producer warp 0 and stole issue slots); publish = R5's tid0 / 32 steps.
// ---------------------------------------------------------------------------

#define TSTEPS 16384
#define NITEMS 1000
#define PUB_CHUNK 32

typedef unsigned long long ull;

// global scratch (device globals: allocation-free per harness rules)
__device__ float g_gx[TSTEPS * 128];   // 8 MB: [t][row(gate*32+elem)] preacts
__device__ float g_ys[TSTEPS * 32];    // 2 MB: time-LSTM hidden states
__device__ float g_H[3][40];           // final hidden per mask type
__device__ int   g_progress;           // producer progress (steps completed)

// ---- fast math helpers ----------------------------------------------------
__device__ __forceinline__ float ftanh_(float x) {
    float y; asm("tanh.approx.f32 %0, %1;" : "=f"(y) : "f"(x)); return y;
}

// ---- scoped sync primitives ----------------------------------------------
__device__ __forceinline__ void fence_gpu() {
    asm volatile("fence.acq_rel.gpu;" ::: "memory");
}
__device__ __forceinline__ void st_relaxed_gpu(int* p, int v) {
    asm volatile("st.relaxed.gpu.global.b32 [%0], %1;" :: "l"(p), "r"(v) : "memory");
}
__device__ __forceinline__ int ld_acquire_gpu(const int* p) {
    int v; asm volatile("ld.acquire.gpu.global.b32 %0, [%1];" : "=r"(v) : "l"(p) : "memory");
    return v;
}
#define BAR_SYNC(id)   asm volatile("bar.sync %0, 128;"   :: "n"(id) : "memory")

// ---- packed f32x2 ops (sm_103a) -------------------------------------------
__device__ __forceinline__ ull pack2(float lo, float hi) {
    ull r; asm("mov.b64 %0, {%1,%2};" : "=l"(r) : "f"(lo), "f"(hi)); return r;
}
__device__ __forceinline__ void unpack2(ull v, float& lo, float& hi) {
    asm("mov.b64 {%0,%1}, %2;" : "=f"(lo), "=f"(hi) : "l"(v));
}
__device__ __forceinline__ void ffma2(ull& acc, ull a, ull b) {
    asm("fma.rn.f32x2 %0, %1, %2, %0;" : "+l"(acc) : "l"(a), "l"(b));
}
__device__ __forceinline__ ull add2(ull a, ull b) {
    ull r; asm("add.rn.f32x2 %0, %1, %2;" : "=l"(r) : "l"(a), "l"(b)); return r;
}
__device__ __forceinline__ ull mul2(ull a, ull b) {
    ull r; asm("mul.rn.f32x2 %0, %1, %2;" : "=l"(r) : "l"(a), "l"(b)); return r;
}
__device__ __forceinline__ float red2(ull v) {
    float lo, hi; unpack2(v, lo, hi); return lo + hi;
}

// ---------------------------------------------------------------------------
// K1: per-t gate preactivations for the time LSTM (fully parallel).
// Row r = gate*32 + elem, stored at g_gx[t*128 + r].
// Sigmoid gates (gate != 2) are PRE-SCALED by 0.5 (sigmoid(z)=0.5*tanh(0.5z)+0.5).
// ---------------------------------------------------------------------------
__global__ void k_precompute_gx(const int* __restrict__ items,
                                const int* __restrict__ types,
                                const float* __restrict__ dwell,
                                const float* __restrict__ item_emb,
                                const float* __restrict__ click,
                                const float* __restrict__ purchase,
                                const float* __restrict__ skip,
                                const float* __restrict__ Wih,
                                const float* __restrict__ bih,
                                const float* __restrict__ bhh)
{
    int t = blockIdx.x;
    int tid = threadIdx.x;   // 128 threads

    if (t == 0 && tid == 0) g_progress = 0;  // reset before pipeline kernel

    __shared__ float ie[32];
    __shared__ float xs[10];

    if (tid < 32) ie[tid] = item_emb[tid * NITEMS + items[t]];
    __syncthreads();

    if (tid < 9) {
        int ty = types[t];
        const float* P = (ty == 0) ? click : (ty == 1) ? purchase : skip;
        P += tid * 32;
        float s = 0.0f;
#pragma unroll
        for (int j = 0; j < 32; j++) s += P[j] * ie[j];
        xs[1 + tid] = s;
    } else if (tid == 9) {
        xs[0] = dwell[t];
    }
    __syncthreads();

    float acc = bih[tid] + bhh[tid];
    const float* w = Wih + tid * 10;
#pragma unroll
    for (int i = 0; i < 10; i++) acc += w[i] * xs[i];
    if ((tid >> 5) != 2) acc *= 0.5f;    // fold sigmoid prescale
    g_gx[t * 128 + tid] = acc;
}

// ---------------------------------------------------------------------------
// K2: persistent pipeline. grid = 4 blocks x 160 threads.
//   block 0: producer (time LSTM), 4 warps; warp w lane l owns
//            gate (l>>3) of element 8w+(l&7).
//   blocks 1..3: consumers for mask types 1 (p), 0 (c), 2 (s)
// ---------------------------------------------------------------------------
__global__ void __launch_bounds__(160, 1)
k_pipeline(const int* __restrict__ types,
           const float* __restrict__ time_Whh,
           const float* __restrict__ p_Wih, const float* __restrict__ p_Whh,
           const float* __restrict__ p_bih, const float* __restrict__ p_bhh,
           const float* __restrict__ c_Wih, const float* __restrict__ c_Whh,
           const float* __restrict__ c_bih, const float* __restrict__ c_bhh,
           const float* __restrict__ s_Wih, const float* __restrict__ s_Whh,
           const float* __restrict__ s_bih, const float* __restrict__ s_bhh)
{
    int tid = threadIdx.x;

    if (blockIdx.x == 0) {
        // ---------------- producer: time LSTM, 4 warps, 1 bar/step --------
        if (tid >= 128) return;           // 5th warp idle; named bar uses 128
        int wid = tid >> 5, l = tid & 31;
        int gate = l >> 3, eloc = l & 7;
        int e = wid * 8 + eloc;           // element 0..31
        int row = gate * 32 + e;          // Whh / gx row
        bool isg = (gate == 2);

        __shared__ __align__(16) float h_buf[2][32];

        ull w2[16];
        {
            const ull* wp = reinterpret_cast<const ull*>(time_Whh + row * 32);
            ull half2c = pack2(0.5f, 0.5f);
#pragma unroll
            for (int i = 0; i < 16; i++) {
                ull w = wp[i];
                w2[i] = isg ? w : mul2(w, half2c);   // fold sigmoid prescale
            }
        }
        float c = 0.0f;
        if (l < 8) h_buf[0][e] = 0.0f;    // lanes 0..7 of each warp init 8 elems
        float gx = g_gx[row];             // t = 0
        BAR_SYNC(1);

        for (int t = 0; t < TSTEPS; t++) {
            // chunked progress publish (R5-style, proven non-intrusive)
            if (tid == 0 && t && ((t & (PUB_CHUNK - 1)) == 0)) {
                fence_gpu(); st_relaxed_gpu(&g_progress, t);
            }
            // prefetch next step's preact (LDG hidden behind the step)
            float gxn = (t + 1 < TSTEPS) ? g_gx[(t + 1) * 128 + row] : 0.0f;

            ull a0 = pack2(gx, 0.0f);
            ull a1 = pack2(0.0f, 0.0f);
            ull a2 = pack2(0.0f, 0.0f);
            ull a3 = pack2(0.0f, 0.0f);
            const ulonglong2* hp = reinterpret_cast<const ulonglong2*>(h_buf[t & 1]);
#pragma unroll
            for (int q = 0; q < 4; q++) {
                ulonglong2 hv0 = hp[2 * q];
                ulonglong2 hv1 = hp[2 * q + 1];
                ffma2(a0, w2[4 * q],     hv0.x);
                ffma2(a1, w2[4 * q + 1], hv0.y);
                ffma2(a2, w2[4 * q + 2], hv1.x);
                ffma2(a3, w2[4 * q + 3], hv1.y);
            }
            float gsum = red2(add2(add2(a0, a1), add2(a2, a3)));
            float tv = ftanh_(gsum);                    // arg already prescaled
            float v = isg ? tv : fmaf(0.5f, tv, 0.5f);

            // intra-warp gate exchange (all gates of elem e live in this warp)
            float iv = __shfl_sync(0xffffffffu, v, eloc);
            float fv = __shfl_sync(0xffffffffu, v, 8 + eloc);
            float gg = __shfl_sync(0xffffffffu, v, 16 + eloc);
            float ov = __shfl_sync(0xffffffffu, v, 24 + eloc);

            c = fmaf(fv, c, iv * gg);          // replicated across gate-lanes
            float h = ov * ftanh_(c);

            if (l < 8) {
                h_buf[(t + 1) & 1][e] = h;
                g_ys[t * 32 + e] = h;
            }
            BAR_SYNC(1);                       // single barrier per step
            gx = gxn;
        }
        if (tid == 0) { fence_gpu(); st_relaxed_gpu(&g_progress, TSTEPS); }
    } else {
        // ---------------- consumer: masked LSTM (R5 structure + fold) ------
        __shared__ unsigned char tysh[TSTEPS];   // 16 KB
        __shared__ __align__(16) float h_sh[40];
        __shared__ __align__(16) float x_sh[32];
        __shared__ float gsh[160];

        int b = blockIdx.x;
        int myType = (b == 1) ? 1 : (b == 2) ? 0 : 2;
        const float* Wih = (b == 1) ? p_Wih : (b == 2) ? c_Wih : s_Wih;
        const float* Whh = (b == 1) ? p_Whh : (b == 2) ? c_Whh : s_Whh;
        const float* bih = (b == 1) ? p_bih : (b == 2) ? c_bih : s_bih;
        const float* bhh = (b == 1) ? p_bhh : (b == 2) ? c_bhh : s_bhh;

        for (int i = tid; i < TSTEPS; i += 160)
            tysh[i] = (unsigned char)types[i];

        bool isg = (tid / 40 == 2);              // rows 80..119 = g-gate
        ull wih2[16], whh2[20];
        {
            ull half2c = pack2(0.5f, 0.5f);
            const ull* p = reinterpret_cast<const ull*>(Wih) + tid * 16;
#pragma unroll
            for (int i = 0; i < 16; i++) { ull w = p[i]; wih2[i] = isg ? w : mul2(w, half2c); }
            const ull* q = reinterpret_cast<const ull*>(Whh) + tid * 20;
#pragma unroll
            for (int i = 0; i < 20; i++) { ull w = q[i]; whh2[i] = isg ? w : mul2(w, half2c); }
        }
        float bsum = bih[tid] + bhh[tid];
        if (!isg) bsum *= 0.5f;
        float c = 0.0f;
        if (tid < 40) h_sh[tid] = 0.0f;
        __syncthreads();

        int seen = 0;
        for (int t = 0; t < TSTEPS; t++) {
            if (tysh[t] != (unsigned char)myType) continue;   // uniform across block

            if (tid == 0 && seen <= t) {
                while ((seen = ld_acquire_gpu(&g_progress)) <= t) { }
            }
            __syncthreads();

            if (tid < 32) x_sh[tid] = __ldcg(&g_ys[t * 32 + tid]);
            __syncthreads();

            // 4 accumulators: dep chains of 8/8/10/10
            ull a0 = pack2(bsum, 0.0f);
            ull a1 = pack2(0.0f, 0.0f);
            ull a2 = pack2(0.0f, 0.0f);
            ull a3 = pack2(0.0f, 0.0f);
            const ulonglong2* xp = reinterpret_cast<const ulonglong2*>(x_sh);
#pragma unroll
            for (int q = 0; q < 8; q++) {
                ffma2(a0, wih2[2 * q], xp[q].x);
                ffma2(a1, wih2[2 * q + 1], xp[q].y);
            }
            const ulonglong2* hp = reinterpret_cast<const ulonglong2*>(h_sh);
#pragma unroll
            for (int q = 0; q < 10; q++) {
                ffma2(a2, whh2[2 * q], hp[q].x);
                ffma2(a3, whh2[2 * q + 1], hp[q].y);
            }
            float g = red2(add2(add2(a0, a1), add2(a2, a3)));
            float tv = ftanh_(g);
            float v = isg ? tv : fmaf(0.5f, tv, 0.5f);
            gsh[tid] = v;
            __syncthreads();

            if (tid < 40) {
                float ig = gsh[tid], fg = gsh[40 + tid];
                float gg = gsh[80 + tid], og = gsh[120 + tid];
                c = fg * c + ig * gg;
                h_sh[tid] = og * ftanh_(c);
            }
            __syncthreads();
        }

        if (tid < 40) g_H[myType][tid] = h_sh[tid];
    }
}

// ---------------------------------------------------------------------------
// K3: fusion + MLP -> scalar
// fusion = [next_e(32), user_e(32), H_r(32), H_s(40), H_c(40), H_p(40)]
// ---------------------------------------------------------------------------
__global__ void k_mlp(const int* __restrict__ user,
                      const int* __restrict__ nextitem,
                      const float* __restrict__ item_emb,
                      const float* __restrict__ user_emb,
                      const float* __restrict__ out1_W,
                      const float* __restrict__ out1_b,
                      const float* __restrict__ out2_W,
                      const float* __restrict__ out2_b,
                      float* __restrict__ out)
{
    __shared__ float f[216];
    __shared__ float r16[16];
    int tid = threadIdx.x;   // 64 threads
    int u = user[0], ni = nextitem[0];

    if (tid < 32) {
        f[tid]      = item_emb[tid * NITEMS + ni];
        f[32 + tid] = user_emb[tid * NITEMS + u];
        f[64 + tid] = g_ys[(TSTEPS - 1) * 32 + tid];   // H_r
    }
    if (tid < 40) {
        f[96 + tid]  = g_H[2][tid];   // H_s (type 2)
        f[136 + tid] = g_H[0][tid];   // H_c (type 0)
        f[176 + tid] = g_H[1][tid];   // H_p (type 1)
    }
    __syncthreads();

    if (tid < 16) {
        float acc = out1_b[tid];
        const float* w = out1_W + tid * 216;
        for (int k = 0; k < 216; k++) acc += w[k] * f[k];
        r16[tid] = fmaxf(acc, 0.0f);
    }
    __syncthreads();

    if (tid == 0) {
        float acc = out2_b[0];
        for (int k = 0; k < 16; k++) acc += out2_W[k] * r16[k];
        out[0] = acc;
    }
}

// ---------------------------------------------------------------------------
extern "C" void kernel_launch(void* const* d_in, const int* in_sizes, int n_in,
                              void* d_out, int out_size)
{
    const int*   user      = (const int*)  d_in[0];
    const int*   nextitem  = (const int*)  d_in[1];
    const int*   seq_items = (const int*)  d_in[2];
    const int*   seq_types = (const int*)  d_in[3];
    const float* dwell     = (const float*)d_in[4];
    const float* item_emb  = (const float*)d_in[5];
    const float* user_emb  = (const float*)d_in[6];
    const float* click     = (const float*)d_in[7];
    const float* purchase  = (const float*)d_in[8];
    const float* skipp     = (const float*)d_in[9];
    const float* time_Wih  = (const float*)d_in[10];
    const float* time_Whh  = (const float*)d_in[11];
    const float* time_bih  = (const float*)d_in[12];
    const float* time_bhh  = (const float*)d_in[13];
    const float* p_Wih     = (const float*)d_in[14];
    const float* p_Whh     = (const float*)d_in[15];
    const float* p_bih     = (const float*)d_in[16];
    const float* p_bhh     = (const float*)d_in[17];
    const float* c_Wih     = (const float*)d_in[18];
    const float* c_Whh     = (const float*)d_in[19];
    const float* c_bih     = (const float*)d_in[20];
    const float* c_bhh     = (const float*)d_in[21];
    const float* s_Wih     = (const float*)d_in[22];
    const float* s_Whh     = (const float*)d_in[23];
    const float* s_bih     = (const float*)d_in[24];
    const float* s_bhh     = (const float*)d_in[25];
    const float* out1_W    = (const float*)d_in[26];
    const float* out1_b    = (const float*)d_in[27];
    const float* out2_W    = (const float*)d_in[28];
    const float* out2_b    = (const float*)d_in[29];

    k_precompute_gx<<<TSTEPS, 128>>>(seq_items, seq_types, dwell, item_emb,
                                     click, purchase, skipp,
                                     time_Wih, time_bih, time_bhh);

    k_pipeline<<<4, 160>>>(seq_types, time_Whh,
                           p_Wih, p_Whh, p_bih, p_bhh,
                           c_Wih, c_Whh, c_bih, c_bhh,
                           s_Wih, s_Whh, s_bih, s_bhh);

    k_mlp<<<1, 64>>>(user, nextitem, item_emb, user_emb,
                     out1_W, out1_b, out2_W, out2_b, (float*)d_out);
}